// round 15
// baseline (speedup 1.0000x reference)
#include <cuda_runtime.h>
#include <cuda_bf16.h>
#include <cuda_fp16.h>
#include <cstdint>

// NOTE: resubmission of R12 (container-level infra failure, kernel never ran).

#define NN 50000
#define EE 800000
#define DH 128
#define NCLS 40

// ---------------- scratch ----------------
__device__ __align__(16) float g_agg[NN * DH];
__device__ __align__(16) float g_h[NN * DH];
__device__ __align__(16) float g_hidden[NN * 2 * DH];
__device__ int g_cnt[NN];
__device__ int g_rowptr[NN];
__device__ int g_cursor[NN];
__device__ int g_col[EE];
__device__ int g_total;
__device__ int g_is64;
// transposed fp16 weights: [N,K]. 4 slots of 32768 elements.
__device__ __align__(16) __half g_wh[4 * 32768];

// ---------------- CSR build (scan-free) ----------------
// zero + dtype detection fused (detection result needed only by count/fill,
// which launch after this kernel completes)
__global__ void zero_int_kernel(int* p, int n, const int* __restrict__ ei32, int n_words) {
    int i = blockIdx.x * blockDim.x + threadIdx.x;
    if (i < n) p[i] = 0;
    if (i == 0) {
        g_total = 0;
        int all_zero = 1;
        for (int k = 0; k < 128; k++) {
            int idx = 2 * k + 1;
            if (idx < n_words && ei32[idx] != 0) { all_zero = 0; break; }
        }
        g_is64 = all_zero;
    }
}

__global__ void count_kernel(const void* __restrict__ ei, int E) {
    int e = blockIdx.x * blockDim.x + threadIdx.x;
    if (e >= E) return;
    int d;
    if (g_is64) d = (int)((const long long*)ei)[E + e];
    else        d = ((const int*)ei)[E + e];
    atomicAdd(&g_cnt[d], 1);
}

__global__ void reserve_kernel(int n) {
    int i = blockIdx.x * blockDim.x + threadIdx.x;
    if (i >= n) return;
    int c = g_cnt[i];
    int s = atomicAdd(&g_total, c);
    g_rowptr[i] = s;
    g_cursor[i] = s;
}

__global__ void fill_kernel(const void* __restrict__ ei, int E) {
    int e = blockIdx.x * blockDim.x + threadIdx.x;
    if (e >= E) return;
    int s, d;
    if (g_is64) {
        s = (int)((const long long*)ei)[e];
        d = (int)((const long long*)ei)[E + e];
    } else {
        s = ((const int*)ei)[e];
        d = ((const int*)ei)[E + e];
    }
    int pos = atomicAdd(&g_cursor[d], 1);
    g_col[pos] = s;
}

// ---------------- aggregation ----------------
__global__ void agg_kernel(const float* __restrict__ x, float* __restrict__ out, int M) {
    int node = blockIdx.x * (blockDim.x >> 5) + (threadIdx.x >> 5);
    if (node >= M) return;
    int lane = threadIdx.x & 31;
    const float4* x4 = (const float4*)x;
    float4* out4 = (float4*)out;
    size_t base = (size_t)node * 32 + lane;
    float4 acc = x4[base];
    int e = g_rowptr[node];
    int end = g_cursor[node];
    for (; e + 4 <= end; e += 4) {
        int s0 = g_col[e], s1 = g_col[e + 1], s2 = g_col[e + 2], s3 = g_col[e + 3];
        float4 v0 = __ldg(&x4[(size_t)s0 * 32 + lane]);
        float4 v1 = __ldg(&x4[(size_t)s1 * 32 + lane]);
        float4 v2 = __ldg(&x4[(size_t)s2 * 32 + lane]);
        float4 v3 = __ldg(&x4[(size_t)s3 * 32 + lane]);
        acc.x += (v0.x + v1.x) + (v2.x + v3.x);
        acc.y += (v0.y + v1.y) + (v2.y + v3.y);
        acc.z += (v0.z + v1.z) + (v2.z + v3.z);
        acc.w += (v0.w + v1.w) + (v2.w + v3.w);
    }
    for (; e < end; e++) {
        int s = g_col[e];
        float4 v = __ldg(&x4[(size_t)s * 32 + lane]);
        acc.x += v.x; acc.y += v.y; acc.z += v.z; acc.w += v.w;
    }
    out4[base] = acc;
}

// ---------------- weight transpose + fp16 convert ----------------
__global__ void conv_w_kernel(const float* __restrict__ W,
                              __half* __restrict__ out, int K, int N) {
    int i = blockIdx.x * blockDim.x + threadIdx.x;
    if (i >= N * K) return;
    int n = i / K, k = i - n * K;
    out[i] = __float2half(W[(size_t)k * N + n]);
}

#define SA 20

__device__ __forceinline__ void mma_fp16(float& c0, float& c1, float& c2, float& c3,
                                         uint32_t a0, uint32_t a1, uint32_t a2, uint32_t a3,
                                         uint32_t b0, uint32_t b1) {
    asm volatile(
        "mma.sync.aligned.m16n8k16.row.col.f32.f16.f16.f32 "
        "{%0,%1,%2,%3}, {%4,%5,%6,%7}, {%8,%9}, {%0,%1,%2,%3};"
        : "+f"(c0), "+f"(c1), "+f"(c2), "+f"(c3)
        : "r"(a0), "r"(a1), "r"(a2), "r"(a3), "r"(b0), "r"(b1));
}

__device__ __forceinline__ void ldsm_x4(uint32_t& r0, uint32_t& r1, uint32_t& r2, uint32_t& r3,
                                        uint32_t addr) {
    asm volatile("ldmatrix.sync.aligned.m8n8.x4.shared.b16 {%0,%1,%2,%3}, [%4];"
                 : "=r"(r0), "=r"(r1), "=r"(r2), "=r"(r3) : "r"(addr));
}
__device__ __forceinline__ void ldsm_x2(uint32_t& r0, uint32_t& r1, uint32_t addr) {
    asm volatile("ldmatrix.sync.aligned.m8n8.x2.shared.b16 {%0,%1}, [%2];"
                 : "=r"(r0), "=r"(r1) : "r"(addr));
}
__device__ __forceinline__ uint32_t smem_addr(const void* p) {
    return (uint32_t)__cvta_generic_to_shared(p);
}

// ---------------- fp16 2-pass GEMM, N=128 tile (proven R11 kernel) ----------------
__global__ __launch_bounds__(256, 2) void fp16_gemm_kernel(
    const float* __restrict__ A,
    const __half* __restrict__ Wh,
    const float* __restrict__ bias,
    float* __restrict__ C,
    int M, int N, int K, int relu)
{
    __shared__ uint32_t Ah[128 * SA];
    __shared__ uint32_t Al[128 * SA];
    __shared__ uint32_t Bh[128 * SA];

    int tid = threadIdx.x;
    int wid = tid >> 5, lane = tid & 31;
    int g = lane >> 2, t4 = lane & 3;
    int warp_m = (wid >> 2) * 64;
    int warp_n = (wid & 3) * 32;
    int br = blockIdx.y * 128, bc = blockIdx.x * 128;

    int row = tid >> 1;
    int ks2 = (tid & 1) * 8;
    bool a_ok = (br + row) < M;
    const float* a_src = A + (size_t)(a_ok ? (br + row) : 0) * K + ks2 * 2;
    const __half* b_src = Wh + (size_t)(bc + row) * K + ks2 * 2;

    uint32_t AhB = smem_addr(Ah), AlB = smem_addr(Al), BhB = smem_addr(Bh);
    uint32_t laneA = ((lane & 15) * SA + (lane >> 4) * 4) * 4;
    uint32_t laneB = ((lane & 7) * SA + ((lane >> 3) & 1) * 4) * 4;

    float acc[4][4][4];
#pragma unroll
    for (int i = 0; i < 4; i++)
#pragma unroll
        for (int j = 0; j < 4; j++)
#pragma unroll
            for (int r = 0; r < 4; r++) acc[i][j][r] = 0.0f;

    float4 f[4];
    uint4 pbh[2];
    {
        if (a_ok) {
            const float4* ap = (const float4*)a_src;
            f[0] = ap[0]; f[1] = ap[1]; f[2] = ap[2]; f[3] = ap[3];
        } else {
            f[0] = f[1] = f[2] = f[3] = make_float4(0.f, 0.f, 0.f, 0.f);
        }
        const uint4* hp = (const uint4*)b_src;
        pbh[0] = hp[0]; pbh[1] = hp[1];
    }

    for (int k0 = 0; k0 < K; k0 += 32) {
        uint32_t rb = row * SA + ks2;
#pragma unroll
        for (int j = 0; j < 4; j++) {
            float xs[4] = {f[j].x, f[j].y, f[j].z, f[j].w};
#pragma unroll
            for (int p = 0; p < 2; p++) {
                float x0 = xs[2 * p], x1 = xs[2 * p + 1];
                __half2 h = __float22half2_rn(make_float2(x0, x1));
                float l0 = x0 - __half2float(__low2half(h));
                float l1 = x1 - __half2float(__high2half(h));
                __half2 l = __float22half2_rn(make_float2(l0, l1));
                Ah[rb + 2 * j + p] = *(uint32_t*)&h;
                Al[rb + 2 * j + p] = *(uint32_t*)&l;
            }
        }
        *(uint4*)&Bh[rb] = pbh[0];
        *(uint4*)&Bh[rb + 4] = pbh[1];
        __syncthreads();

        if (k0 + 32 < K) {
            a_src += 32; b_src += 32;
            if (a_ok) {
                const float4* ap = (const float4*)a_src;
                f[0] = ap[0]; f[1] = ap[1]; f[2] = ap[2]; f[3] = ap[3];
            }
            const uint4* hp = (const uint4*)b_src;
            pbh[0] = hp[0]; pbh[1] = hp[1];
        }

#pragma unroll
        for (int s = 0; s < 2; s++) {
            int so = s * 8;
            uint32_t ah[4][4], al[4][4];
#pragma unroll
            for (int mt = 0; mt < 4; mt++) {
                uint32_t off = (uint32_t)(((warp_m + mt * 16) * SA + so) * 4);
                ldsm_x4(ah[mt][0], ah[mt][1], ah[mt][2], ah[mt][3], AhB + off + laneA);
                ldsm_x4(al[mt][0], al[mt][1], al[mt][2], al[mt][3], AlB + off + laneA);
            }
#pragma unroll
            for (int nt = 0; nt < 4; nt++) {
                uint32_t boff = (uint32_t)(((warp_n + nt * 8) * SA + so) * 4);
                uint32_t bh0, bh1;
                ldsm_x2(bh0, bh1, BhB + boff + laneB);
#pragma unroll
                for (int mt = 0; mt < 4; mt++) {
                    float* cc = acc[mt][nt];
                    mma_fp16(cc[0], cc[1], cc[2], cc[3],
                             ah[mt][0], ah[mt][1], ah[mt][2], ah[mt][3], bh0, bh1);
                    mma_fp16(cc[0], cc[1], cc[2], cc[3],
                             al[mt][0], al[mt][1], al[mt][2], al[mt][3], bh0, bh1);
                }
            }
        }
        __syncthreads();
    }

#pragma unroll
    for (int mt = 0; mt < 4; mt++) {
#pragma unroll
        for (int nt = 0; nt < 4; nt++) {
            int r0 = br + warp_m + mt * 16 + g;
            int cc = bc + warp_n + nt * 8 + 2 * t4;
            float2 bv = *(const float2*)&bias[cc];
            float* a = acc[mt][nt];
            if (r0 < M) {
                float2 v = make_float2(a[0] + bv.x, a[1] + bv.y);
                if (relu) { v.x = fmaxf(v.x, 0.f); v.y = fmaxf(v.y, 0.f); }
                *(float2*)&C[(size_t)r0 * N + cc] = v;
            }
            int r1 = r0 + 8;
            if (r1 < M) {
                float2 v = make_float2(a[2] + bv.x, a[3] + bv.y);
                if (relu) { v.x = fmaxf(v.x, 0.f); v.y = fmaxf(v.y, 0.f); }
                *(float2*)&C[(size_t)r1 * N + cc] = v;
            }
        }
    }
}

// ---------------- fp16 2-pass GEMM, N=256 tile, 512 threads / 16 warps ----------------
// Warp grid 2(m) x 8(n), warp tile 64x32, acc 64 regs -> ~120 regs/thread,
// 16 warps resident per SM (2x latency hiding vs the 256-thread version).
__global__ __launch_bounds__(512, 1) void fp16_gemm256_kernel(
    const float* __restrict__ A,
    const __half* __restrict__ Wh,
    const float* __restrict__ bias,
    float* __restrict__ C,
    int M, int K, int relu)
{
    const int N = 256;
    __shared__ uint32_t Ah[128 * SA];
    __shared__ uint32_t Al[128 * SA];
    __shared__ uint32_t Bh[256 * SA];

    int tid = threadIdx.x;
    int wid = tid >> 5, lane = tid & 31;
    int g = lane >> 2, t4 = lane & 3;
    int warp_m = (wid & 1) * 64;        // 0 or 64
    int warp_n = (wid >> 1) * 32;       // 0..224
    int br = blockIdx.y * 128;

    // A load: 4 threads per row, each 8 floats (4 uints after split)
    int row = tid >> 2;                 // 0..127
    int ks2 = (tid & 3) * 4;            // uint offset {0,4,8,12}
    bool a_ok = (br + row) < M;
    const float* a_src = A + (size_t)(a_ok ? (br + row) : 0) * K + ks2 * 2;
    // B load: 2 threads per N-row, each 8 uints
    int brow = tid >> 1;                // 0..255
    int bks = (tid & 1) * 8;
    const __half* b_src = Wh + (size_t)brow * K + bks * 2;

    uint32_t AhB = smem_addr(Ah), AlB = smem_addr(Al), BhB = smem_addr(Bh);
    uint32_t laneA = ((lane & 15) * SA + (lane >> 4) * 4) * 4;
    uint32_t laneB = ((lane & 7) * SA + ((lane >> 3) & 1) * 4) * 4;

    float acc[4][4][4];
#pragma unroll
    for (int i = 0; i < 4; i++)
#pragma unroll
        for (int j = 0; j < 4; j++)
#pragma unroll
            for (int r = 0; r < 4; r++) acc[i][j][r] = 0.0f;

    // prefetch tile 0
    float4 f[2];
    uint4 pb[2];
    {
        if (a_ok) {
            const float4* ap = (const float4*)a_src;
            f[0] = ap[0]; f[1] = ap[1];
        } else {
            f[0] = f[1] = make_float4(0.f, 0.f, 0.f, 0.f);
        }
        const uint4* hp = (const uint4*)b_src;
        pb[0] = hp[0]; pb[1] = hp[1];
    }

    for (int k0 = 0; k0 < K; k0 += 32) {
        // staged regs -> smem
        uint32_t rb = row * SA + ks2;
#pragma unroll
        for (int j = 0; j < 2; j++) {
            float xs[4] = {f[j].x, f[j].y, f[j].z, f[j].w};
#pragma unroll
            for (int p = 0; p < 2; p++) {
                float x0 = xs[2 * p], x1 = xs[2 * p + 1];
                __half2 h = __float22half2_rn(make_float2(x0, x1));
                float l0 = x0 - __half2float(__low2half(h));
                float l1 = x1 - __half2float(__high2half(h));
                __half2 l = __float22half2_rn(make_float2(l0, l1));
                Ah[rb + 2 * j + p] = *(uint32_t*)&h;
                Al[rb + 2 * j + p] = *(uint32_t*)&l;
            }
        }
        {
            uint32_t bb = brow * SA + bks;
            *(uint4*)&Bh[bb]     = pb[0];
            *(uint4*)&Bh[bb + 4] = pb[1];
        }
        __syncthreads();

        // prefetch next
        if (k0 + 32 < K) {
            a_src += 32; b_src += 32;
            if (a_ok) {
                const float4* ap = (const float4*)a_src;
                f[0] = ap[0]; f[1] = ap[1];
            }
            const uint4* hp = (const uint4*)b_src;
            pb[0] = hp[0]; pb[1] = hp[1];
        }

        // compute: 2 k16-slices, warp tile 64x32
#pragma unroll
        for (int s = 0; s < 2; s++) {
            int so = s * 8;
            uint32_t ah[4][4], al[4][4];
#pragma unroll
            for (int mt = 0; mt < 4; mt++) {
                uint32_t off = (uint32_t)(((warp_m + mt * 16) * SA + so) * 4);
                ldsm_x4(ah[mt][0], ah[mt][1], ah[mt][2], ah[mt][3], AhB + off + laneA);
                ldsm_x4(al[mt][0], al[mt][1], al[mt][2], al[mt][3], AlB + off + laneA);
            }
#pragma unroll
            for (int nt = 0; nt < 4; nt++) {
                uint32_t boff = (uint32_t)(((warp_n + nt * 8) * SA + so) * 4);
                uint32_t bh0, bh1;
                ldsm_x2(bh0, bh1, BhB + boff + laneB);
#pragma unroll
                for (int mt = 0; mt < 4; mt++) {
                    float* cc = acc[mt][nt];
                    mma_fp16(cc[0], cc[1], cc[2], cc[3],
                             ah[mt][0], ah[mt][1], ah[mt][2], ah[mt][3], bh0, bh1);
                    mma_fp16(cc[0], cc[1], cc[2], cc[3],
                             al[mt][0], al[mt][1], al[mt][2], al[mt][3], bh0, bh1);
                }
            }
        }
        __syncthreads();
    }

    // epilogue
#pragma unroll
    for (int mt = 0; mt < 4; mt++) {
#pragma unroll
        for (int nt = 0; nt < 4; nt++) {
            int r0 = br + warp_m + mt * 16 + g;
            int cc = warp_n + nt * 8 + 2 * t4;
            float2 bv = *(const float2*)&bias[cc];
            float* a = acc[mt][nt];
            if (r0 < M) {
                float2 v = make_float2(a[0] + bv.x, a[1] + bv.y);
                if (relu) { v.x = fmaxf(v.x, 0.f); v.y = fmaxf(v.y, 0.f); }
                *(float2*)&C[(size_t)r0 * N + cc] = v;
            }
            int r1 = r0 + 8;
            if (r1 < M) {
                float2 v = make_float2(a[2] + bv.x, a[3] + bv.y);
                if (relu) { v.x = fmaxf(v.x, 0.f); v.y = fmaxf(v.y, 0.f); }
                *(float2*)&C[(size_t)r1 * N + cc] = v;
            }
        }
    }
}

// ---------------- classifier ----------------
__global__ __launch_bounds__(256) void fc40_kernel(
    const float* __restrict__ A, const float* __restrict__ W,
    const float* __restrict__ bias, float* __restrict__ out, int M)
{
    __shared__ float Ws[DH * NCLS];
    for (int i = threadIdx.x; i < DH * NCLS; i += blockDim.x) Ws[i] = W[i];
    __syncthreads();

    int row = blockIdx.x * blockDim.x + threadIdx.x;
    if (row >= M) return;

    float acc[NCLS];
#pragma unroll
    for (int j = 0; j < NCLS; j++) acc[j] = bias[j];

    const float4* __restrict__ a4 = (const float4*)(A + (size_t)row * DH);
#pragma unroll 8
    for (int kc = 0; kc < DH / 4; kc++) {
        float4 av = a4[kc];
        int k = kc * 4;
        const float* w0 = &Ws[(k + 0) * NCLS];
        const float* w1 = &Ws[(k + 1) * NCLS];
        const float* w2 = &Ws[(k + 2) * NCLS];
        const float* w3 = &Ws[(k + 3) * NCLS];
#pragma unroll
        for (int j = 0; j < NCLS; j++)
            acc[j] += av.x * w0[j] + av.y * w1[j] + av.z * w2[j] + av.w * w3[j];
    }
    float* o = out + (size_t)row * NCLS;
#pragma unroll
    for (int j = 0; j < NCLS; j++) o[j] = acc[j];
}

// ---------------- launch ----------------
extern "C" void kernel_launch(void* const* d_in, const int* in_sizes, int n_in,
                              void* d_out, int out_size)
{
    const float* x    = (const float*)d_in[0];
    const void*  ei   = d_in[1];
    const float* W11  = (const float*)d_in[2];
    const float* b11  = (const float*)d_in[3];
    const float* W12  = (const float*)d_in[4];
    const float* b12  = (const float*)d_in[5];
    const float* W21  = (const float*)d_in[6];
    const float* b21  = (const float*)d_in[7];
    const float* W22  = (const float*)d_in[8];
    const float* b22  = (const float*)d_in[9];
    const float* Wfc  = (const float*)d_in[10];
    const float* bfc  = (const float*)d_in[11];

    int M = in_sizes[0] / DH;      // 50000
    int E = in_sizes[1] / 2;       // 800000

    float *p_agg, *p_h, *p_hidden;
    cudaGetSymbolAddress((void**)&p_agg, g_agg);
    cudaGetSymbolAddress((void**)&p_h, g_h);
    cudaGetSymbolAddress((void**)&p_hidden, g_hidden);
    int* p_cnt;
    cudaGetSymbolAddress((void**)&p_cnt, g_cnt);
    __half* p_wh;
    cudaGetSymbolAddress((void**)&p_wh, g_wh);

    // CSR build (zero kernel also detects edge dtype)
    zero_int_kernel<<<(M + 255) / 256, 256>>>(p_cnt, M, (const int*)ei, 2 * E);
    count_kernel<<<(E + 255) / 256, 256>>>(ei, E);
    reserve_kernel<<<(M + 255) / 256, 256>>>(M);
    fill_kernel<<<(E + 255) / 256, 256>>>(ei, E);

    // weight transpose + fp16 convert
    const int WS = 32768;
    conv_w_kernel<<<WS / 256, 256>>>(W11, p_wh + 0 * WS, 128, 256);
    conv_w_kernel<<<WS / 256, 256>>>(W12, p_wh + 1 * WS, 256, 128);
    conv_w_kernel<<<WS / 256, 256>>>(W21, p_wh + 2 * WS, 128, 256);
    conv_w_kernel<<<WS / 256, 256>>>(W22, p_wh + 3 * WS, 256, 128);

    int agg_blocks = (M + 7) / 8;
    dim3 g1(1, (M + 127) / 128);   // N=256 full-width tiles
    dim3 g2(1, (M + 127) / 128);   // N=128

    // Layer 1
    agg_kernel<<<agg_blocks, 256>>>(x, p_agg, M);
    fp16_gemm256_kernel<<<g1, 512>>>(p_agg, p_wh + 0 * WS, b11, p_hidden, M, 128, 1);
    fp16_gemm_kernel<<<g2, 256>>>(p_hidden, p_wh + 1 * WS, b12, p_h, M, 128, 256, 1);

    // Layer 2
    agg_kernel<<<agg_blocks, 256>>>(p_h, p_agg, M);
    fp16_gemm256_kernel<<<g1, 512>>>(p_agg, p_wh + 2 * WS, b21, p_hidden, M, 128, 1);
    fp16_gemm_kernel<<<g2, 256>>>(p_hidden, p_wh + 3 * WS, b22, p_h, M, 128, 256, 1);

    // Classifier
    fc40_kernel<<<(M + 255) / 256, 256>>>(p_h, Wfc, bfc, (float*)d_out, M);
}